// round 15
// baseline (speedup 1.0000x reference)
#include <cuda_runtime.h>
#include <math.h>
#include <cstdint>

// ---------------- problem constants ----------------
#define N_TOT   65536      // B*H*W
#define K_CB    512
#define KH      256        // codes per half
#define C_DIM   64
#define B_DIM   64
#define HW      1024

#define TM      64         // rows per tile (8 pairs x 8 rows)
#define THREADS 512
#define NWARP   16
#define NTILES  1024
#define NCTAS   152        // persistent, 1 CTA/SM
#define WROW    514        // wT row stride (floats)

// output layout (floats), concatenation of the reference tuple
#define Q_OFF     0ULL
#define LOSS_OFF  4194304ULL
#define PERP_OFF  4194368ULL
#define ENC_OFF   4194369ULL
#define EIDX_OFF  37748801ULL
#define DIST_OFF  37814337ULL
#define OUT_TOTAL 71368769

// smem layout (float indices)
#define SM_WT   0                      // wT[64][514] = 32896 floats
#define SM_XW   32896                  // per-warp x slices: 16 warps x 2 bufs x 512 = 16384
#define SM_WN   (SM_XW + 16384)        // wnorm[512]
#define SM_CANB (SM_WN + 512)          // float candb[64][2]
#define SM_CANI (SM_CANB + 128)        // int   candi[64][2]
#define SM_RED  (SM_CANI + 128)        // float red[512] (finish only)
#define SM_TOTF (SM_RED + 512)
#define SMEM_BYTES (SM_TOTF * 4)       // ~202 KB -> 1 CTA/SM

__device__ float g_lp[NTILES * NWARP]; // per (tile, warp) loss partial
__device__ int   g_hist[K_CB];         // zero at load; last CTA re-zeroes each launch
__device__ int   g_done;               // arrival ticket; last CTA resets

typedef unsigned long long ull;

// ---------------- helpers ----------------
__device__ __forceinline__ ull pack2(float x) {
    ull r; asm("mov.b64 %0, {%1, %1};" : "=l"(r) : "f"(x)); return r;
}
__device__ __forceinline__ void fma2(ull &d, ull a, ull b) {
    asm("fma.rn.f32x2 %0, %1, %2, %3;" : "=l"(d) : "l"(a), "l"(b), "l"(d));
}
__device__ __forceinline__ void unpack2(ull v, float &lo, float &hi) {
    asm("mov.b64 {%0, %1}, %2;" : "=f"(lo), "=f"(hi) : "l"(v));
}
__device__ __forceinline__ uint32_t smem_u32(const void* p) {
    uint32_t a;
    asm("{ .reg .u64 t; cvta.to.shared.u64 t, %1; cvt.u32.u64 %0, t; }" : "=r"(a) : "l"(p));
    return a;
}
#define CP_ASYNC16(sa, gp) asm volatile("cp.async.cg.shared.global [%0], [%1], 16;" :: "r"(sa), "l"(gp))
#define CP_COMMIT()        asm volatile("cp.async.commit_group;" ::: "memory")
#define CP_WAIT1()         asm volatile("cp.async.wait_group 1;" ::: "memory")
#define CP_WAIT0()         asm volatile("cp.async.wait_group 0;" ::: "memory")
// pairwise named barrier: 2 warps (64 threads), id in 1..8
#define PAIR_BAR(id)       asm volatile("bar.sync %0, 64;" :: "r"(id) : "memory")

// ---------------- single persistent kernel: warp-pairs, half-codebook each ----------------
extern "C" __global__ void __launch_bounds__(THREADS, 1)
vq_all(const float* __restrict__ inputs, const float* __restrict__ weight,
       float* __restrict__ out)
{
    extern __shared__ float smem[];
    float* wT    = smem + SM_WT;       // wT[c][k]
    float* wnorm = smem + SM_WN;
    float* candb = smem + SM_CANB;     // [row][half]
    int*   candi = (int*)(smem + SM_CANI);
    float* red   = smem + SM_RED;

    const int tid  = threadIdx.x;
    const int warp = tid >> 5;
    const int lane = tid & 31;
    const int q    = warp >> 1;        // pair index: rows 8q..8q+7
    const int half = warp & 1;         // codebook half
    const int cta  = blockIdx.x;

    float* xw_base = smem + SM_XW + warp * 1024;        // 2 slices x 512 floats: [c][8]
    const uint32_t xw_sa = smem_u32(xw_base);

    // per-thread cp.async channels: c = lane and c = lane+32 (2x16B each)
    const int c0 = lane, c1 = lane + 32;

    // ---- prefetch first tile's slice into buf 0 (pair rows, duplicated per warp) ----
    {
        const int t0 = cta;
        const float* src = inputs + (size_t)(t0 >> 4) * (C_DIM * HW)
                         + (t0 & 15) * 64 + 8 * q;
        CP_ASYNC16(xw_sa + (uint32_t)(c0 * 8) * 4,     src + (size_t)c0 * HW);
        CP_ASYNC16(xw_sa + (uint32_t)(c0 * 8 + 4) * 4, src + (size_t)c0 * HW + 4);
        CP_ASYNC16(xw_sa + (uint32_t)(c1 * 8) * 4,     src + (size_t)c1 * HW);
        CP_ASYNC16(xw_sa + (uint32_t)(c1 * 8 + 4) * 4, src + (size_t)c1 * HW + 4);
        CP_COMMIT();
    }

    // ---- one-time: weight transpose + wnorm (the only CTA barriers) ----
    for (int i = tid; i < K_CB * C_DIM; i += THREADS) {
        int k = i >> 6, c = i & 63;
        wT[c * WROW + k] = weight[i];
    }
    __syncthreads();
    {
        float s = 0.f;
        #pragma unroll
        for (int c = 0; c < C_DIM; c++) { float w = wT[c * WROW + tid]; s = fmaf(w, w, s); }
        wnorm[tid] = s;
    }
    __syncthreads();

    // ---- per-warp persistent tile loop (pairwise named barriers only) ----
    int buf = 0;
    for (int t = cta; t < NTILES; t += NCTAS) {
        // prefetch next tile's slice into the other buffer
        {
            int tn = t + NCTAS; if (tn >= NTILES) tn = 0;
            const float* src = inputs + (size_t)(tn >> 4) * (C_DIM * HW)
                             + (tn & 15) * 64 + 8 * q;
            uint32_t dst = xw_sa + (uint32_t)((buf ^ 1) * 512) * 4;
            CP_ASYNC16(dst + (uint32_t)(c0 * 8) * 4,     src + (size_t)c0 * HW);
            CP_ASYNC16(dst + (uint32_t)(c0 * 8 + 4) * 4, src + (size_t)c0 * HW + 4);
            CP_ASYNC16(dst + (uint32_t)(c1 * 8) * 4,     src + (size_t)c1 * HW);
            CP_ASYNC16(dst + (uint32_t)(c1 * 8 + 4) * 4, src + (size_t)c1 * HW + 4);
            CP_COMMIT();
        }
        CP_WAIT1();                    // current buffer's copies done (this thread)
        __syncwarp();                  // visible warp-wide (own slice only)

        const float* slice = xw_base + buf * 512;   // [c][8] floats

        // xnorm for pair rows: lane r (<8) computes row r (sequential fmaf rounding)
        float xn_own = 0.f;
        if (lane < 8) {
            #pragma unroll
            for (int c = 0; c < C_DIM; c++) {
                float x = slice[c * 8 + lane];
                xn_own = fmaf(x, x, xn_own);
            }
        }

        // ---- mainloop: 8 rows x 8 codes per lane over this HALF ----
        // local codes kl = 2*lane + 64*j, j=0..3; global k = half*256 + kl
        ull acc[8][4];
        #pragma unroll
        for (int r = 0; r < 8; r++)
            #pragma unroll
            for (int j = 0; j < 4; j++) acc[r][j] = 0ULL;

        const ull* bbase = (const ull*)(wT + half * KH + 2 * lane);

        #pragma unroll 4
        for (int c = 0; c < C_DIM; c++) {
            const float4 a0 = *(const float4*)(slice + c * 8);       // rows 0-3
            const float4 a1 = *(const float4*)(slice + c * 8 + 4);   // rows 4-7
            ull aa[8];
            aa[0] = pack2(a0.x); aa[1] = pack2(a0.y); aa[2] = pack2(a0.z); aa[3] = pack2(a0.w);
            aa[4] = pack2(a1.x); aa[5] = pack2(a1.y); aa[6] = pack2(a1.z); aa[7] = pack2(a1.w);
            const ull* bp = bbase + (size_t)c * (WROW / 2);
            ull bb[4];
            #pragma unroll
            for (int j = 0; j < 4; j++) bb[j] = bp[32 * j];          // conflict-free LDS.64
            #pragma unroll
            for (int r = 0; r < 8; r++)
                #pragma unroll
                for (int j = 0; j < 4; j++) fma2(acc[r][j], aa[r], bb[j]);
        }

        const int n0   = t * TM + 8 * q;          // first row of this pair
        const int bimg = t >> 4;
        const int p0   = (t & 15) * 64 + 8 * q;

        // ---- epilogue: distances (reference rounding) + per-half warp argmin ----
        const float INF = __int_as_float(0x7f800000);
        #pragma unroll
        for (int r = 0; r < 8; r++) {
            const int n = n0 + r;
            const float xn = __shfl_sync(0xffffffffu, xn_own, r);

            float best = INF; int bidx = 0;
            float* dptr = out + DIST_OFF + (size_t)n * K_CB + half * KH;
            #pragma unroll
            for (int j = 0; j < 4; j++) {
                float zlo, zhi; unpack2(acc[r][j], zlo, zhi);
                const int kl = 2 * lane + 64 * j;
                const float2 wn2 = *(const float2*)(wnorm + half * KH + kl);
                float dlo = (xn + wn2.x) - 2.0f * zlo;
                float dhi = (xn + wn2.y) - 2.0f * zhi;
                __stcs(dptr + kl,     dlo);                       // coalesced pairs
                __stcs(dptr + kl + 1, dhi);
                if (dlo < best) { best = dlo; bidx = kl; }        // ascending k, strict '<'
                if (dhi < best) { best = dhi; bidx = kl + 1; }    // -> lowest index on ties
            }
            #pragma unroll
            for (int off = 16; off > 0; off >>= 1) {
                float ob = __shfl_xor_sync(0xffffffffu, best, off);
                int   oi = __shfl_xor_sync(0xffffffffu, bidx, off);
                if (ob < best || (ob == best && oi < bidx)) { best = ob; bidx = oi; }
            }
            if (lane == 0) {
                candb[(8 * q + r) * 2 + half] = best;
                candi[(8 * q + r) * 2 + half] = half * KH + bidx;
            }
        }

        // ---- pairwise handshake: both halves' candidates visible ----
        PAIR_BAR(q + 1);

        // combine halves (half0 indices all lower -> strict '<' keeps lowest index)
        int bi_own = 0;
        if (lane < 8) {
            const int row = 8 * q + lane;
            float b0 = candb[row * 2], b1 = candb[row * 2 + 1];
            int   i0 = candi[row * 2], i1 = candi[row * 2 + 1];
            bi_own = (b1 < b0) ? i1 : i0;
            if (half == 0) {
                out[EIDX_OFF + (size_t)(n0 + lane)] = (float)bi_own;
                atomicAdd(&g_hist[bi_own], 1);           // order-independent
            }
        }
        PAIR_BAR(q + 1);                                 // reads done before next-tile writes

        int bi_r[8];
        #pragma unroll
        for (int r = 0; r < 8; r++) bi_r[r] = __shfl_sync(0xffffffffu, bi_own, r);

        // ---- encodings: each warp of the pair does 4 rows (float4 interior + 4 scalars) ----
        {
            float* ebase = out + ENC_OFF + (size_t)n0 * K_CB;
            #pragma unroll
            for (int rr = 0; rr < 4; rr++) {
                const int rl = half * 4 + rr;
                const int sv = bi_r[rl];
                float* rbase = ebase + (size_t)rl * K_CB;
                #pragma unroll
                for (int m = lane; m < 127; m += 32) {
                    const int k = 3 + 4 * m;
                    float4 v;
                    v.x = (sv == k)     ? 1.0f : 0.0f;
                    v.y = (sv == k + 1) ? 1.0f : 0.0f;
                    v.z = (sv == k + 2) ? 1.0f : 0.0f;
                    v.w = (sv == k + 3) ? 1.0f : 0.0f;
                    __stcs((float4*)(rbase + k), v);   // 16B aligned (ENC_OFF odd + 3)
                }
                if (lane < 3)       rbase[lane] = (sv == lane) ? 1.0f : 0.0f;
                else if (lane == 3) rbase[511]  = (sv == 511)  ? 1.0f : 0.0f;
            }
        }

        // ---- q_out: each warp does 32 channels (c = half*32 + lane) for the 8 rows ----
        float s = 0.f;
        {
            const int c = half * 32 + lane;
            float4 xa = *(const float4*)(slice + c * 8);
            float4 xb = *(const float4*)(slice + c * 8 + 4);
            const float* wrow = wT + c * WROW;
            float d0 = wrow[bi_r[0]] - xa.x;
            float d1 = wrow[bi_r[1]] - xa.y;
            float d2 = wrow[bi_r[2]] - xa.z;
            float d3 = wrow[bi_r[3]] - xa.w;
            float d4 = wrow[bi_r[4]] - xb.x;
            float d5 = wrow[bi_r[5]] - xb.y;
            float d6 = wrow[bi_r[6]] - xb.z;
            float d7 = wrow[bi_r[7]] - xb.w;
            float4 oa, ob;
            oa.x = xa.x + d0; oa.y = xa.y + d1; oa.z = xa.z + d2; oa.w = xa.w + d3;
            ob.x = xb.x + d4; ob.y = xb.y + d5; ob.z = xb.z + d6; ob.w = xb.w + d7;
            float* qp = out + (size_t)bimg * (C_DIM * HW) + (size_t)c * HW + p0;
            __stcs((float4*)qp, oa);
            __stcs((float4*)(qp + 4), ob);
            s = fmaf(d0, d0, s); s = fmaf(d1, d1, s);
            s = fmaf(d2, d2, s); s = fmaf(d3, d3, s);
            s = fmaf(d4, d4, s); s = fmaf(d5, d5, s);
            s = fmaf(d6, d6, s); s = fmaf(d7, d7, s);
        }
        #pragma unroll
        for (int off = 16; off > 0; off >>= 1) s += __shfl_xor_sync(0xffffffffu, s, off);
        if (lane == 0) g_lp[t * NWARP + warp] = s;

        __syncwarp();                  // slice reads done before next-iter prefetch reuse
        buf ^= 1;
    }
    CP_WAIT0();                        // drain dangling prefetch

    // ---- fused finish: last CTA computes loss + perplexity ----
    __syncthreads();
    __shared__ int s_last;
    if (tid == 0) {
        __threadfence();
        s_last = (atomicAdd(&g_done, 1) == NCTAS - 1);
    }
    __syncthreads();
    if (s_last) {
        if (tid == 0) g_done = 0;                 // reset for graph replay
        if (tid < B_DIM) {
            float s = 0.f;
            #pragma unroll
            for (int j = 0; j < 16; j++)          // tiles of batch, fixed order
                #pragma unroll
                for (int w = 0; w < NWARP; w++)   // warp partials, fixed order
                    s += g_lp[(tid * 16 + j) * NWARP + w];
            out[LOSS_OFF + tid] = 1.25f * (s * (1.0f / 65536.0f));
        }
        int h = g_hist[tid];
        g_hist[tid] = 0;                          // restore zero invariant
        float p = (float)h * (1.0f / 65536.0f);
        red[tid] = -p * logf(p + 1e-10f);
        __syncthreads();
        #pragma unroll
        for (int off = 256; off > 0; off >>= 1) {
            if (tid < off) red[tid] += red[tid + off];
            __syncthreads();
        }
        if (tid == 0) out[PERP_OFF] = expf(red[0]);
    }
}

// ---------------- launch ----------------
extern "C" void kernel_launch(void* const* d_in, const int* in_sizes, int n_in,
                              void* d_out, int out_size)
{
    const float* inputs = (const float*)d_in[0];
    const float* weight = (const float*)d_in[1];
    float* out = (float*)d_out;

    if (out_size != OUT_TOTAL) return;

    cudaFuncSetAttribute(vq_all, cudaFuncAttributeMaxDynamicSharedMemorySize, SMEM_BYTES);

    vq_all<<<NCTAS, THREADS, SMEM_BYTES>>>(inputs, weight, out);
}